// round 8
// baseline (speedup 1.0000x reference)
#include <cuda_runtime.h>
#include <cuda_bf16.h>
#include <cstdint>

#define NN 500000
#define ND 128
#define NH 64
#define NG 16384
#define NB 128                     // nodes per CTA
#define TB 128                     // 4 warps, 32 nodes per warp
#define NT ((NN + NB - 1) / NB)    // 3907 CTAs

#define APITCH 136                 // bf16 elems per row (272B = 17*16B: LDSM conflict-free)
#define WPITCH 136
#define A_BYTES (NB * APITCH * 2)  // 34816
#define W_BYTES (NH * WPITCH * 2)  // 17408
#define SMEM_DYN (A_BYTES + W_BYTES)   // 52224 -> 4 CTAs/SM

__device__ int g_batch_is64;

// Zero graph-energy slots; detect batch dtype (word NN-1 is the zero int64
// high half iff batch stored as int64).
__global__ void init_kernel(float* __restrict__ out, const int* __restrict__ bw) {
    int i = blockIdx.x * blockDim.x + threadIdx.x;
    if (i < NG) out[NN + i] = 0.0f;
    if (i == 0) g_batch_is64 = (bw[NN - 1] == 0) ? 1 : 0;
}

__device__ __forceinline__ uint32_t smem_u32(const void* p) {
    uint32_t a;
    asm("{ .reg .u64 t; cvta.to.shared.u64 t, %1; cvt.u32.u64 %0, t; }" : "=r"(a) : "l"(p));
    return a;
}

// Pack 8 fp32 (two float4) -> 4 x bf16x2 (RN)
__device__ __forceinline__ uint4 pack8_bf16(float4 f0, float4 f1) {
    uint4 u;
    __nv_bfloat162 h;
    h = __floats2bfloat162_rn(f0.x, f0.y); u.x = *(uint32_t*)&h;
    h = __floats2bfloat162_rn(f0.z, f0.w); u.y = *(uint32_t*)&h;
    h = __floats2bfloat162_rn(f1.x, f1.y); u.z = *(uint32_t*)&h;
    h = __floats2bfloat162_rn(f1.z, f1.w); u.w = *(uint32_t*)&h;
    return u;
}

__device__ __forceinline__ void ldsm4(uint32_t* r, uint32_t addr) {
    asm volatile("ldmatrix.sync.aligned.m8n8.x4.shared.b16 {%0,%1,%2,%3}, [%4];"
                 : "=r"(r[0]), "=r"(r[1]), "=r"(r[2]), "=r"(r[3]) : "r"(addr));
}

__device__ __forceinline__ void mma16816(float* d, const uint32_t* a,
                                         uint32_t b0, uint32_t b1) {
    asm volatile(
        "mma.sync.aligned.m16n8k16.row.col.f32.bf16.bf16.f32 "
        "{%0,%1,%2,%3}, {%4,%5,%6,%7}, {%8,%9}, {%0,%1,%2,%3};"
        : "+f"(d[0]), "+f"(d[1]), "+f"(d[2]), "+f"(d[3])
        : "r"(a[0]), "r"(a[1]), "r"(a[2]), "r"(a[3]), "r"(b0), "r"(b1));
}

__device__ __forceinline__ float silu(float h) {
    return h * __frcp_rn(1.0f + __expf(-h));
}

__global__ __launch_bounds__(TB, 4)
void mlp_kernel(const float* __restrict__ X,
                const float* __restrict__ aein,
                const void*  __restrict__ batch,
                const float* __restrict__ W1,
                const float* __restrict__ b1,
                const float* __restrict__ W2,
                const float* __restrict__ b2,
                float* __restrict__ out)
{
    extern __shared__ char smraw[];
    __nv_bfloat16* As = (__nv_bfloat16*)smraw;
    __nv_bfloat16* Ws = (__nv_bfloat16*)(smraw + A_BYTES);
    __shared__ float b1s[NH], w2s[NH];

    const int tid  = threadIdx.x;
    const int lane = tid & 31;
    const int wid  = tid >> 5;
    const long node0 = (long)blockIdx.x * NB;

    // ---- Stage X tile: 2x LDG.128 -> bf16 -> 1x STS.128 (16 per thread) ----
    #pragma unroll
    for (int q = 0; q < 16; q++) {
        int idx = tid + q * TB;          // 2048 groups of 8 floats
        int row = idx >> 4;
        int g8  = idx & 15;
        long gn = node0 + row;
        uint4 u = make_uint4(0u, 0u, 0u, 0u);
        if (gn < NN) {
            const float4* p = (const float4*)(X + gn * (long)ND + g8 * 8);
            u = pack8_bf16(p[0], p[1]);
        }
        *(uint4*)(As + row * APITCH + g8 * 8) = u;
    }
    // ---- Stage W1 (8 per thread) ----
    #pragma unroll
    for (int q = 0; q < 8; q++) {
        int idx = tid + q * TB;          // 1024 groups
        int row = idx >> 4;
        int g8  = idx & 15;
        const float4* p = (const float4*)(W1 + (size_t)row * ND + g8 * 8);
        *(uint4*)(Ws + row * WPITCH + g8 * 8) = pack8_bf16(p[0], p[1]);
    }
    if (tid < NH) { b1s[tid] = b1[tid]; w2s[tid] = W2[tid]; }
    __syncthreads();

    const uint32_t smA = smem_u32(As), smW = smem_u32(Ws);
    const int g  = lane >> 2;
    const int tg = lane & 3;

    // ---- Load all A fragments: 2 node-tiles x 8 k-steps (64 regs) ----
    uint32_t af[2][8][4];
    {
        const int ahalf = (lane >> 4) * 8;
        #pragma unroll
        for (int t = 0; t < 2; t++) {
            const int arow = wid * 32 + t * 16 + (lane & 15);
            #pragma unroll
            for (int k = 0; k < 8; k++)
                ldsm4(af[t][k], smA + (uint32_t)((arow * APITCH + k * 16 + ahalf) * 2));
        }
    }

    // ---- GEMM + fused epilogue over 4 col-tile pairs ----
    float ps[2][2] = {{0.f, 0.f}, {0.f, 0.f}};   // [node-tile][row g / g+8]
    const int bline = (lane & 7) + ((lane >> 4) << 3);
    const int bkoff = (lane & 8) ? 8 : 0;
    #pragma unroll
    for (int jp = 0; jp < 4; jp++) {
        float acc[2][2][4];                      // [node-tile][n-half][frag]
        #pragma unroll
        for (int t = 0; t < 2; t++)
            #pragma unroll
            for (int h = 0; h < 2; h++)
                acc[t][h][0] = acc[t][h][1] = acc[t][h][2] = acc[t][h][3] = 0.f;
        #pragma unroll
        for (int k = 0; k < 8; k++) {
            uint32_t bf[4];
            ldsm4(bf, smW + (uint32_t)(((jp * 16 + bline) * WPITCH + k * 16 + bkoff) * 2));
            #pragma unroll
            for (int t = 0; t < 2; t++) {
                mma16816(acc[t][0], af[t][k], bf[0], bf[1]);
                mma16816(acc[t][1], af[t][k], bf[2], bf[3]);
            }
        }
        #pragma unroll
        for (int t = 0; t < 2; t++) {
            #pragma unroll
            for (int h = 0; h < 2; h++) {
                int c0 = (jp * 2 + h) * 8 + tg * 2;
                float2 bv = *(const float2*)(b1s + c0);
                float2 wv = *(const float2*)(w2s + c0);
                ps[t][0] = fmaf(silu(acc[t][h][0] + bv.x), wv.x, ps[t][0]);
                ps[t][0] = fmaf(silu(acc[t][h][1] + bv.y), wv.y, ps[t][0]);
                ps[t][1] = fmaf(silu(acc[t][h][2] + bv.x), wv.x, ps[t][1]);
                ps[t][1] = fmaf(silu(acc[t][h][3] + bv.y), wv.y, ps[t][1]);
            }
        }
    }
    // reduce across the 4 threads sharing each row (tg = 0..3)
    #pragma unroll
    for (int t = 0; t < 2; t++) {
        #pragma unroll
        for (int r = 0; r < 2; r++) {
            ps[t][r] += __shfl_xor_sync(0xFFFFFFFFu, ps[t][r], 1);
            ps[t][r] += __shfl_xor_sync(0xFFFFFFFFu, ps[t][r], 2);
        }
    }

    if (tg == 0) {
        float bb = __ldg(b2);
        #pragma unroll
        for (int t = 0; t < 2; t++) {
            #pragma unroll
            for (int r = 0; r < 2; r++) {
                long gn = node0 + wid * 32 + t * 16 + r * 8 + g;
                if (gn < NN) {
                    float e = ps[t][r] + bb + __ldg(aein + gn);
                    out[gn] = e;
                    int gr;
                    if (g_batch_is64) gr = (int)((const long long*)batch)[gn];
                    else              gr = ((const int*)batch)[gn];
                    atomicAdd(out + NN + gr, e);
                }
            }
        }
    }
}

extern "C" void kernel_launch(void* const* d_in, const int* in_sizes, int n_in,
                              void* d_out, int out_size) {
    const float* X     = (const float*)d_in[0];
    const float* aein  = (const float*)d_in[1];
    const void*  batch = d_in[2];
    const float* W1    = (const float*)d_in[3];
    const float* b1    = (const float*)d_in[4];
    const float* W2    = (const float*)d_in[5];
    const float* b2    = (const float*)d_in[6];
    float* out = (float*)d_out;

    cudaFuncSetAttribute(mlp_kernel, cudaFuncAttributeMaxDynamicSharedMemorySize,
                         SMEM_DYN);

    init_kernel<<<(NG + 255) / 256, 256>>>(out, (const int*)batch);
    mlp_kernel<<<NT, TB, SMEM_DYN>>>(X, aein, batch, W1, b1, W2, b2, out);
}

// round 9
// speedup vs baseline: 1.5298x; 1.5298x over previous
#include <cuda_runtime.h>
#include <cuda_bf16.h>
#include <cstdint>

#define NN 500000
#define ND 128
#define NH 64
#define NG 16384
#define NB 128                     // nodes per CTA
#define TB 256                     // 8 warps, 16 nodes per warp
#define NT ((NN + NB - 1) / NB)    // 3907 CTAs

#define WPITCH 136                 // bf16 per W row (272B = 17*16B: LDSM conflict-free)

__device__ int g_batch_is64;

// Zero graph-energy slots; detect batch dtype (word NN-1 is the zero int64
// high half iff batch stored as int64).
__global__ void init_kernel(float* __restrict__ out, const int* __restrict__ bw) {
    int i = blockIdx.x * blockDim.x + threadIdx.x;
    if (i < NG) out[NN + i] = 0.0f;
    if (i == 0) g_batch_is64 = (bw[NN - 1] == 0) ? 1 : 0;
}

__device__ __forceinline__ uint32_t smem_u32(const void* p) {
    uint32_t a;
    asm("{ .reg .u64 t; cvta.to.shared.u64 t, %1; cvt.u32.u64 %0, t; }" : "=r"(a) : "l"(p));
    return a;
}

__device__ __forceinline__ uint32_t pack2(float2 f) {   // lo half = f.x
    __nv_bfloat162 h = __floats2bfloat162_rn(f.x, f.y);
    return *(uint32_t*)&h;
}

__device__ __forceinline__ uint4 pack8_bf16(float4 f0, float4 f1) {
    uint4 u;
    __nv_bfloat162 h;
    h = __floats2bfloat162_rn(f0.x, f0.y); u.x = *(uint32_t*)&h;
    h = __floats2bfloat162_rn(f0.z, f0.w); u.y = *(uint32_t*)&h;
    h = __floats2bfloat162_rn(f1.x, f1.y); u.z = *(uint32_t*)&h;
    h = __floats2bfloat162_rn(f1.z, f1.w); u.w = *(uint32_t*)&h;
    return u;
}

__device__ __forceinline__ void ldsm4(uint32_t* r, uint32_t addr) {
    asm volatile("ldmatrix.sync.aligned.m8n8.x4.shared.b16 {%0,%1,%2,%3}, [%4];"
                 : "=r"(r[0]), "=r"(r[1]), "=r"(r[2]), "=r"(r[3]) : "r"(addr));
}

__device__ __forceinline__ void mma16816(float* d, const uint32_t* a,
                                         uint32_t b0, uint32_t b1) {
    asm volatile(
        "mma.sync.aligned.m16n8k16.row.col.f32.bf16.bf16.f32 "
        "{%0,%1,%2,%3}, {%4,%5,%6,%7}, {%8,%9}, {%0,%1,%2,%3};"
        : "+f"(d[0]), "+f"(d[1]), "+f"(d[2]), "+f"(d[3])
        : "r"(a[0]), "r"(a[1]), "r"(a[2]), "r"(a[3]), "r"(b0), "r"(b1));
}

__device__ __forceinline__ float silu(float h) {
    return h * __frcp_rn(1.0f + __expf(-h));
}

__global__ __launch_bounds__(TB, 4)
void mlp_kernel(const float* __restrict__ X,
                const float* __restrict__ aein,
                const void*  __restrict__ batch,
                const float* __restrict__ W1,
                const float* __restrict__ b1,
                const float* __restrict__ W2,
                const float* __restrict__ b2,
                float* __restrict__ out)
{
    __shared__ __nv_bfloat16 Ws[NH * WPITCH];   // 17408 B
    __shared__ float b1s[NH], w2s[NH];

    const int tid  = threadIdx.x;
    const int lane = tid & 31;
    const int wid  = tid >> 5;
    const long node0 = (long)blockIdx.x * NB;
    const int g  = lane >> 2;
    const int tg = lane & 3;

    // ---- Stage W1 (bf16 RN), 4 STS.128 per thread ----
    #pragma unroll
    for (int q = 0; q < 4; q++) {
        int idx = tid + q * TB;          // 1024 groups of 8 floats
        int row = idx >> 4;
        int g8  = idx & 15;
        const float4* p = (const float4*)(W1 + (size_t)row * ND + g8 * 8);
        *(uint4*)(Ws + row * WPITCH + g8 * 8) = pack8_bf16(p[0], p[1]);
    }
    if (tid < NH) { b1s[tid] = b1[tid]; w2s[tid] = W2[tid]; }

    // ---- A fragments straight from global X (no smem round trip) ----
    // m16n8k16 A layout: a0=(row g, col tg*2), a1=(row g+8), a2=(row g, +8),
    // a3=(row g+8, +8). Clamp OOB rows: their outputs are never stored.
    long rg  = node0 + wid * 16 + g;
    long rg8 = rg + 8;
    long rgc  = rg  < NN ? rg  : (NN - 1);
    long rg8c = rg8 < NN ? rg8 : (NN - 1);
    const float* pA0 = X + rgc  * (long)ND + tg * 2;
    const float* pA1 = X + rg8c * (long)ND + tg * 2;

    uint32_t af[8][4];
    #pragma unroll
    for (int k = 0; k < 8; k++) {
        af[k][0] = pack2(*(const float2*)(pA0 + k * 16));
        af[k][1] = pack2(*(const float2*)(pA1 + k * 16));
        af[k][2] = pack2(*(const float2*)(pA0 + k * 16 + 8));
        af[k][3] = pack2(*(const float2*)(pA1 + k * 16 + 8));
    }
    __syncthreads();    // W tile ready

    const uint32_t smW = smem_u32(Ws);

    // ---- GEMM + fused epilogue over 4 col-tile pairs ----
    float ps0 = 0.0f, ps1 = 0.0f;
    const int bline = (lane & 7) + ((lane >> 4) << 3);
    const int bkoff = (lane & 8) ? 8 : 0;
    #pragma unroll
    for (int jp = 0; jp < 4; jp++) {
        float acc0[4] = {0.f, 0.f, 0.f, 0.f};
        float acc1[4] = {0.f, 0.f, 0.f, 0.f};
        #pragma unroll
        for (int k = 0; k < 8; k++) {
            uint32_t bf[4];
            ldsm4(bf, smW + (uint32_t)(((jp * 16 + bline) * WPITCH + k * 16 + bkoff) * 2));
            mma16816(acc0, af[k], bf[0], bf[1]);
            mma16816(acc1, af[k], bf[2], bf[3]);
        }
        #pragma unroll
        for (int t = 0; t < 2; t++) {
            const float* ac = t ? acc1 : acc0;
            int c0 = (jp * 2 + t) * 8 + tg * 2;
            float2 bv = *(const float2*)(b1s + c0);
            float2 wv = *(const float2*)(w2s + c0);
            ps0 = fmaf(silu(ac[0] + bv.x), wv.x, ps0);
            ps0 = fmaf(silu(ac[1] + bv.y), wv.y, ps0);
            ps1 = fmaf(silu(ac[2] + bv.x), wv.x, ps1);
            ps1 = fmaf(silu(ac[3] + bv.y), wv.y, ps1);
        }
    }
    // reduce across the 4 threads sharing each row (tg = 0..3)
    ps0 += __shfl_xor_sync(0xFFFFFFFFu, ps0, 1);
    ps0 += __shfl_xor_sync(0xFFFFFFFFu, ps0, 2);
    ps1 += __shfl_xor_sync(0xFFFFFFFFu, ps1, 1);
    ps1 += __shfl_xor_sync(0xFFFFFFFFu, ps1, 2);

    if (tg == 0) {
        float bb = __ldg(b2);
        if (rg < NN) {
            float e = ps0 + bb + __ldg(aein + rg);
            out[rg] = e;
            int gr;
            if (g_batch_is64) gr = (int)((const long long*)batch)[rg];
            else              gr = ((const int*)batch)[rg];
            atomicAdd(out + NN + gr, e);
        }
        if (rg8 < NN) {
            float e = ps1 + bb + __ldg(aein + rg8);
            out[rg8] = e;
            int gr;
            if (g_batch_is64) gr = (int)((const long long*)batch)[rg8];
            else              gr = ((const int*)batch)[rg8];
            atomicAdd(out + NN + gr, e);
        }
    }
}

extern "C" void kernel_launch(void* const* d_in, const int* in_sizes, int n_in,
                              void* d_out, int out_size) {
    const float* X     = (const float*)d_in[0];
    const float* aein  = (const float*)d_in[1];
    const void*  batch = d_in[2];
    const float* W1    = (const float*)d_in[3];
    const float* b1    = (const float*)d_in[4];
    const float* W2    = (const float*)d_in[5];
    const float* b2    = (const float*)d_in[6];
    float* out = (float*)d_out;

    init_kernel<<<(NG + 255) / 256, 256>>>(out, (const int*)batch);
    mlp_kernel<<<NT, TB>>>(X, aein, batch, W1, b1, W2, b2, out);
}

// round 10
// speedup vs baseline: 1.5529x; 1.0151x over previous
#include <cuda_runtime.h>
#include <cuda_bf16.h>
#include <cstdint>

#define NN 500000
#define ND 128
#define NH 64
#define NG 16384
#define NB 128                     // nodes per CTA
#define TB 256                     // 8 warps, 16 nodes per warp
#define NT ((NN + NB - 1) / NB)    // 3907 CTAs

#define WPITCH 136                 // bf16 per W row (272B = 17*16B: LDSM conflict-free)

__device__ int g_batch_is64;

// Zero graph-energy slots; detect batch dtype (word NN-1 is the zero int64
// high half iff batch stored as int64).
__global__ void init_kernel(float* __restrict__ out, const int* __restrict__ bw) {
    int i = blockIdx.x * blockDim.x + threadIdx.x;
    if (i < NG) out[NN + i] = 0.0f;
    if (i == 0) g_batch_is64 = (bw[NN - 1] == 0) ? 1 : 0;
}

__device__ __forceinline__ uint32_t smem_u32(const void* p) {
    uint32_t a;
    asm("{ .reg .u64 t; cvta.to.shared.u64 t, %1; cvt.u32.u64 %0, t; }" : "=r"(a) : "l"(p));
    return a;
}

__device__ __forceinline__ uint32_t pack2(float x, float y) {   // lo half = x
    __nv_bfloat162 h = __floats2bfloat162_rn(x, y);
    return *(uint32_t*)&h;
}

__device__ __forceinline__ void ldsm4(uint32_t* r, uint32_t addr) {
    asm volatile("ldmatrix.sync.aligned.m8n8.x4.shared.b16 {%0,%1,%2,%3}, [%4];"
                 : "=r"(r[0]), "=r"(r[1]), "=r"(r[2]), "=r"(r[3]) : "r"(addr));
}

__device__ __forceinline__ void mma16816(float* d, const uint32_t* a,
                                         uint32_t b0, uint32_t b1) {
    asm volatile(
        "mma.sync.aligned.m16n8k16.row.col.f32.bf16.bf16.f32 "
        "{%0,%1,%2,%3}, {%4,%5,%6,%7}, {%8,%9}, {%0,%1,%2,%3};"
        : "+f"(d[0]), "+f"(d[1]), "+f"(d[2]), "+f"(d[3])
        : "r"(a[0]), "r"(a[1]), "r"(a[2]), "r"(a[3]), "r"(b0), "r"(b1));
}

__device__ __forceinline__ float silu(float h) {
    return h * __frcp_rn(1.0f + __expf(-h));
}

// K-permutation (within each 16-col chunk): thread tg supplies logical cols
// {2tg,2tg+1,2tg+8,2tg+9}, which we map to physical cols {4tg..4tg+3} so A
// fragments come from ONE float4 per row. W1 is staged with the same
// permutation: physical pair p (0..7 in-group) -> logical slot (p&1)*4+(p>>1).

__global__ __launch_bounds__(TB, 4)
void mlp_kernel(const float* __restrict__ X,
                const float* __restrict__ aein,
                const void*  __restrict__ batch,
                const float* __restrict__ W1,
                const float* __restrict__ b1,
                const float* __restrict__ W2,
                const float* __restrict__ b2,
                float* __restrict__ out)
{
    __shared__ __nv_bfloat16 Ws[NH * WPITCH];   // 17408 B (k-permuted layout)
    __shared__ float b1s[NH], w2s[NH];

    const int tid  = threadIdx.x;
    const int lane = tid & 31;
    const int wid  = tid >> 5;
    const long node0 = (long)blockIdx.x * NB;
    const int g  = lane >> 2;
    const int tg = lane & 3;

    // ---- Stage W1 (bf16 RN), k-permuted: 16 pair-scatters per thread ----
    #pragma unroll
    for (int q = 0; q < 16; q++) {
        int idx = tid + q * TB;          // 4096 pairs total
        int row = idx >> 6;              // W1 row j (0..63)
        int p   = idx & 63;              // physical pair within row
        int grp = p >> 3;                // 16-col chunk
        int pp  = p & 7;
        int lq  = ((pp & 1) << 2) | (pp >> 1);   // logical pair slot
        float2 v = *(const float2*)(W1 + (size_t)row * ND + p * 2);
        *(uint32_t*)(Ws + row * WPITCH + grp * 16 + lq * 2) = pack2(v.x, v.y);
    }
    if (tid < NH) { b1s[tid] = b1[tid]; w2s[tid] = W2[tid]; }

    // ---- A fragments from global X: one LDG.128 per row per k-step ----
    long rg  = node0 + wid * 16 + g;
    long rg8 = rg + 8;
    long rgc  = rg  < NN ? rg  : (NN - 1);   // clamp: OOB rows never stored
    long rg8c = rg8 < NN ? rg8 : (NN - 1);
    const float* pA0 = X + rgc  * (long)ND + tg * 4;
    const float* pA1 = X + rg8c * (long)ND + tg * 4;

    uint32_t af[8][4];
    #pragma unroll
    for (int k = 0; k < 8; k++) {
        float4 f0 = *(const float4*)(pA0 + k * 16);
        float4 f1 = *(const float4*)(pA1 + k * 16);
        af[k][0] = pack2(f0.x, f0.y);    // logical (2tg,2tg+1), row g
        af[k][2] = pack2(f0.z, f0.w);    // logical (2tg+8,2tg+9), row g
        af[k][1] = pack2(f1.x, f1.y);    // row g+8
        af[k][3] = pack2(f1.z, f1.w);
    }
    __syncthreads();    // W tile ready

    const uint32_t smW = smem_u32(Ws);

    // ---- GEMM + fused epilogue over 4 col-tile pairs ----
    float ps0 = 0.0f, ps1 = 0.0f;
    const int bline = (lane & 7) + ((lane >> 4) << 3);
    const int bkoff = (lane & 8) ? 8 : 0;
    #pragma unroll
    for (int jp = 0; jp < 4; jp++) {
        float acc0[4] = {0.f, 0.f, 0.f, 0.f};
        float acc1[4] = {0.f, 0.f, 0.f, 0.f};
        #pragma unroll
        for (int k = 0; k < 8; k++) {
            uint32_t bf[4];
            ldsm4(bf, smW + (uint32_t)(((jp * 16 + bline) * WPITCH + k * 16 + bkoff) * 2));
            mma16816(acc0, af[k], bf[0], bf[1]);
            mma16816(acc1, af[k], bf[2], bf[3]);
        }
        #pragma unroll
        for (int t = 0; t < 2; t++) {
            const float* ac = t ? acc1 : acc0;
            int c0 = (jp * 2 + t) * 8 + tg * 2;
            float2 bv = *(const float2*)(b1s + c0);
            float2 wv = *(const float2*)(w2s + c0);
            ps0 = fmaf(silu(ac[0] + bv.x), wv.x, ps0);
            ps0 = fmaf(silu(ac[1] + bv.y), wv.y, ps0);
            ps1 = fmaf(silu(ac[2] + bv.x), wv.x, ps1);
            ps1 = fmaf(silu(ac[3] + bv.y), wv.y, ps1);
        }
    }
    // reduce across the 4 threads sharing each row (tg = 0..3)
    ps0 += __shfl_xor_sync(0xFFFFFFFFu, ps0, 1);
    ps0 += __shfl_xor_sync(0xFFFFFFFFu, ps0, 2);
    ps1 += __shfl_xor_sync(0xFFFFFFFFu, ps1, 1);
    ps1 += __shfl_xor_sync(0xFFFFFFFFu, ps1, 2);

    if (tg == 0) {
        float bb = __ldg(b2);
        if (rg < NN) {
            float e = ps0 + bb + __ldg(aein + rg);
            out[rg] = e;
            int gr;
            if (g_batch_is64) gr = (int)((const long long*)batch)[rg];
            else              gr = ((const int*)batch)[rg];
            atomicAdd(out + NN + gr, e);
        }
        if (rg8 < NN) {
            float e = ps1 + bb + __ldg(aein + rg8);
            out[rg8] = e;
            int gr;
            if (g_batch_is64) gr = (int)((const long long*)batch)[rg8];
            else              gr = ((const int*)batch)[rg8];
            atomicAdd(out + NN + gr, e);
        }
    }
}

extern "C" void kernel_launch(void* const* d_in, const int* in_sizes, int n_in,
                              void* d_out, int out_size) {
    const float* X     = (const float*)d_in[0];
    const float* aein  = (const float*)d_in[1];
    const void*  batch = d_in[2];
    const float* W1    = (const float*)d_in[3];
    const float* b1    = (const float*)d_in[4];
    const float* W2    = (const float*)d_in[5];
    const float* b2    = (const float*)d_in[6];
    float* out = (float*)d_out;

    init_kernel<<<(NG + 255) / 256, 256>>>(out, (const int*)batch);
    mlp_kernel<<<NT, TB>>>(X, aein, batch, W1, b1, W2, b2, out);
}

// round 11
// speedup vs baseline: 1.9679x; 1.2672x over previous
#include <cuda_runtime.h>
#include <cuda_bf16.h>
#include <cstdint>

#define NN 500000
#define ND 128
#define NH 64
#define NG 16384
#define NB 256                     // nodes per CTA (2 halves of 128)
#define TB 256                     // 8 warps, 16 nodes per warp per half
#define NT ((NN + NB - 1) / NB)    // 1954 CTAs

#define WPITCH 136                 // bf16 per W row (272B = 17*16B: LDSM conflict-free)

__device__ int g_batch_is64;

// Zero graph-energy slots; detect batch dtype (word NN-1 is the zero int64
// high half iff batch stored as int64).
__global__ void init_kernel(float* __restrict__ out, const int* __restrict__ bw) {
    int i = blockIdx.x * blockDim.x + threadIdx.x;
    if (i < NG) out[NN + i] = 0.0f;
    if (i == 0) g_batch_is64 = (bw[NN - 1] == 0) ? 1 : 0;
}

__device__ __forceinline__ uint32_t smem_u32(const void* p) {
    uint32_t a;
    asm("{ .reg .u64 t; cvta.to.shared.u64 t, %1; cvt.u32.u64 %0, t; }" : "=r"(a) : "l"(p));
    return a;
}

__device__ __forceinline__ uint32_t pack2(float x, float y) {   // lo half = x
    __nv_bfloat162 h = __floats2bfloat162_rn(x, y);
    return *(uint32_t*)&h;
}

__device__ __forceinline__ void ldsm4(uint32_t* r, uint32_t addr) {
    asm volatile("ldmatrix.sync.aligned.m8n8.x4.shared.b16 {%0,%1,%2,%3}, [%4];"
                 : "=r"(r[0]), "=r"(r[1]), "=r"(r[2]), "=r"(r[3]) : "r"(addr));
}

__device__ __forceinline__ void mma16816(float* d, const uint32_t* a,
                                         uint32_t b0, uint32_t b1) {
    asm volatile(
        "mma.sync.aligned.m16n8k16.row.col.f32.bf16.bf16.f32 "
        "{%0,%1,%2,%3}, {%4,%5,%6,%7}, {%8,%9}, {%0,%1,%2,%3};"
        : "+f"(d[0]), "+f"(d[1]), "+f"(d[2]), "+f"(d[3])
        : "r"(a[0]), "r"(a[1]), "r"(a[2]), "r"(a[3]), "r"(b0), "r"(b1));
}

__device__ __forceinline__ float tanhf_approx(float x) {
    float y;
    asm("tanh.approx.f32 %0, %1;" : "=f"(y) : "f"(x));
    return y;
}

// K-permutation (per 16-col chunk): thread tg supplies logical cols
// {2tg,2tg+1,2tg+8,2tg+9} -> physical {4tg..4tg+3}, so A fragments are one
// float4 per row. W1 staged with the same permutation:
// physical pair p (0..7 in-group) -> logical slot (p&1)*4 + (p>>1).

__global__ __launch_bounds__(TB, 4)
void mlp_kernel(const float* __restrict__ X,
                const float* __restrict__ aein,
                const void*  __restrict__ batch,
                const float* __restrict__ W1,
                const float* __restrict__ b1,
                const float* __restrict__ W2,
                const float* __restrict__ b2,
                float* __restrict__ out)
{
    __shared__ __nv_bfloat16 Ws[NH * WPITCH];   // 17408 B (k-permuted)
    __shared__ float b1s[NH], w2h[NH];          // w2h = W2 * 0.5

    const int tid  = threadIdx.x;
    const int lane = tid & 31;
    const int wid  = tid >> 5;
    const long node0 = (long)blockIdx.x * NB;
    const int g  = lane >> 2;
    const int tg = lane & 3;

    // ---- Stage W1 once (bf16 RN, k-permuted) ----
    #pragma unroll
    for (int q = 0; q < 16; q++) {
        int idx = tid + q * TB;          // 4096 pairs
        int row = idx >> 6;
        int p   = idx & 63;
        int grp = p >> 3;
        int pp  = p & 7;
        int lq  = ((pp & 1) << 2) | (pp >> 1);
        float2 v = *(const float2*)(W1 + (size_t)row * ND + p * 2);
        *(uint32_t*)(Ws + row * WPITCH + grp * 16 + lq * 2) = pack2(v.x, v.y);
    }
    if (tid < NH) { b1s[tid] = b1[tid]; w2h[tid] = 0.5f * W2[tid]; }
    __syncthreads();

    const uint32_t smW = smem_u32(Ws);
    const int bline = (lane & 7) + ((lane >> 4) << 3);
    const int bkoff = (lane & 8) ? 8 : 0;
    const float bb = __ldg(b2);

    #pragma unroll 1
    for (int half = 0; half < 2; half++) {
        // ---- A fragments from global X: one LDG.128 per row per k-step ----
        long rg  = node0 + half * 128 + wid * 16 + g;
        long rg8 = rg + 8;
        long rgc  = rg  < NN ? rg  : (NN - 1);   // clamp: OOB never stored
        long rg8c = rg8 < NN ? rg8 : (NN - 1);
        const float* pA0 = X + rgc  * (long)ND + tg * 4;
        const float* pA1 = X + rg8c * (long)ND + tg * 4;

        uint32_t af[8][4];
        #pragma unroll
        for (int k = 0; k < 8; k++) {
            float4 f0 = *(const float4*)(pA0 + k * 16);
            float4 f1 = *(const float4*)(pA1 + k * 16);
            af[k][0] = pack2(f0.x, f0.y);
            af[k][2] = pack2(f0.z, f0.w);
            af[k][1] = pack2(f1.x, f1.y);
            af[k][3] = pack2(f1.z, f1.w);
        }

        // ---- GEMM + fused epilogue over 4 col-tile pairs ----
        float ps0 = 0.0f, ps1 = 0.0f;
        #pragma unroll
        for (int jp = 0; jp < 4; jp++) {
            float acc0[4] = {0.f, 0.f, 0.f, 0.f};
            float acc1[4] = {0.f, 0.f, 0.f, 0.f};
            #pragma unroll
            for (int k = 0; k < 8; k++) {
                uint32_t bf[4];
                ldsm4(bf, smW + (uint32_t)(((jp * 16 + bline) * WPITCH + k * 16 + bkoff) * 2));
                mma16816(acc0, af[k], bf[0], bf[1]);
                mma16816(acc1, af[k], bf[2], bf[3]);
            }
            // silu(h)*w2 = (h*w2/2) * (1 + tanh(h/2)); 1 MUFU per h
            #pragma unroll
            for (int t = 0; t < 2; t++) {
                const float* ac = t ? acc1 : acc0;
                int c0 = (jp * 2 + t) * 8 + tg * 2;
                float2 bv = *(const float2*)(b1s + c0);
                float2 wv = *(const float2*)(w2h + c0);
                {
                    float h = ac[0] + bv.x, hw = h * wv.x;
                    ps0 = fmaf(hw, tanhf_approx(0.5f * h), ps0 + hw);
                }
                {
                    float h = ac[1] + bv.y, hw = h * wv.y;
                    ps0 = fmaf(hw, tanhf_approx(0.5f * h), ps0 + hw);
                }
                {
                    float h = ac[2] + bv.x, hw = h * wv.x;
                    ps1 = fmaf(hw, tanhf_approx(0.5f * h), ps1 + hw);
                }
                {
                    float h = ac[3] + bv.y, hw = h * wv.y;
                    ps1 = fmaf(hw, tanhf_approx(0.5f * h), ps1 + hw);
                }
            }
        }
        // reduce across the 4 threads sharing each row (tg = 0..3)
        ps0 += __shfl_xor_sync(0xFFFFFFFFu, ps0, 1);
        ps0 += __shfl_xor_sync(0xFFFFFFFFu, ps0, 2);
        ps1 += __shfl_xor_sync(0xFFFFFFFFu, ps1, 1);
        ps1 += __shfl_xor_sync(0xFFFFFFFFu, ps1, 2);

        if (tg == 0) {
            if (rg < NN) {
                float e = ps0 + bb + __ldg(aein + rg);
                out[rg] = e;
                int gr;
                if (g_batch_is64) gr = (int)((const long long*)batch)[rg];
                else              gr = ((const int*)batch)[rg];
                atomicAdd(out + NN + gr, e);
            }
            if (rg8 < NN) {
                float e = ps1 + bb + __ldg(aein + rg8);
                out[rg8] = e;
                int gr;
                if (g_batch_is64) gr = (int)((const long long*)batch)[rg8];
                else              gr = ((const int*)batch)[rg8];
                atomicAdd(out + NN + gr, e);
            }
        }
    }
}

extern "C" void kernel_launch(void* const* d_in, const int* in_sizes, int n_in,
                              void* d_out, int out_size) {
    const float* X     = (const float*)d_in[0];
    const float* aein  = (const float*)d_in[1];
    const void*  batch = d_in[2];
    const float* W1    = (const float*)d_in[3];
    const float* b1    = (const float*)d_in[4];
    const float* W2    = (const float*)d_in[5];
    const float* b2    = (const float*)d_in[6];
    float* out = (float*)d_out;

    init_kernel<<<(NG + 255) / 256, 256>>>(out, (const int*)batch);
    mlp_kernel<<<NT, TB>>>(X, aein, batch, W1, b1, W2, b2, out);
}